// round 1
// baseline (speedup 1.0000x reference)
#include <cuda_runtime.h>
#include <math.h>

// Problem constants
#define B_TOTAL 16384
#define F_DIM   512
#define P_DIM   128
#define C_DIM   10
#define MT      128   // rows per block
#define KC      16    // K chunk

// Shared memory layout (in floats)
#define SARR_STRIDE 129
#define SARR_OFF    0                       // 128*129 = 16512
#define AS_OFF      16512                   // KC*128 = 2048
#define BS_OFF      (AS_OFF + KC*128)       // 2048
#define XNORM_OFF   (BS_OFF + KC*128)       // 128
#define WNORM_OFF   (XNORM_OFF + 128)       // 128
#define GAMMA_OFF   (WNORM_OFF + 128)       // 128
#define ALPHA_OFF   (GAMMA_OFF + 128)       // 128
#define U_OFF       (ALPHA_OFF + 128)       // 10*128 = 1280
#define RED_OFF     (U_OFF + C_DIM*128)     // 128*16 = 2048
#define RMAX_OFF    (RED_OFF + 128*16)      // 128
#define SMEM_FLOATS (RMAX_OFF + 128)
#define SMEM_BYTES  (SMEM_FLOATS * 4)

__global__ __launch_bounds__(256, 1)
void ds_fused_kernel(const float* __restrict__ x,
                     const float* __restrict__ w,
                     const float* __restrict__ eta,
                     const float* __restrict__ xi,
                     const float* __restrict__ beta,
                     float* __restrict__ out)
{
    extern __shared__ float sm[];
    const int tid = threadIdx.x;
    const int tx  = tid & 15;     // 16 col-threads
    const int ty  = tid >> 4;     // 16 row-threads
    const int blockRow = blockIdx.x * MT;

    // ---------------- Prologue: per-p quantities + xnorm (threads < 128) ----
    if (tid < P_DIM) {
        const int p = tid;
        float e = eta[p];
        sm[GAMMA_OFF + p] = e * e;
        sm[ALPHA_OFF + p] = 1.0f / (1.0f + expf(-xi[p]));

        // ||w_p||^2  (4 independent partial sums)
        {
            float s0 = 0.f, s1 = 0.f, s2 = 0.f, s3 = 0.f;
            const float4* wr = (const float4*)(w + (size_t)p * F_DIM);
            #pragma unroll 8
            for (int i = 0; i < F_DIM / 4; ++i) {
                float4 v = wr[i];
                s0 += v.x * v.x; s1 += v.y * v.y; s2 += v.z * v.z; s3 += v.w * v.w;
            }
            sm[WNORM_OFF + p] = (s0 + s1) + (s2 + s3);
        }
        // u[c][p] = beta^2 / sum_c beta^2
        {
            float b2[C_DIM]; float bs = 0.f;
            #pragma unroll
            for (int c = 0; c < C_DIM; ++c) {
                float bv = beta[c * P_DIM + p];
                b2[c] = bv * bv; bs += b2[c];
            }
            float binv = 1.0f / bs;
            #pragma unroll
            for (int c = 0; c < C_DIM; ++c) sm[U_OFF + c * P_DIM + p] = b2[c] * binv;
        }
        // ||x_row||^2 for this block's row p
        {
            float s0 = 0.f, s1 = 0.f, s2 = 0.f, s3 = 0.f;
            const float4* xr = (const float4*)(x + (size_t)(blockRow + p) * F_DIM);
            #pragma unroll 8
            for (int i = 0; i < F_DIM / 4; ++i) {
                float4 v = xr[i];
                s0 += v.x * v.x; s1 += v.y * v.y; s2 += v.z * v.z; s3 += v.w * v.w;
            }
            sm[XNORM_OFF + p] = (s0 + s1) + (s2 + s3);
        }
    }

    // ---------------- GEMM: acc[i][j] = x_row(m) . w_row(n) ----------------
    float acc[8][8];
    #pragma unroll
    for (int i = 0; i < 8; ++i)
        #pragma unroll
        for (int j = 0; j < 8; ++j) acc[i][j] = 0.f;

    const float* xblk = x + (size_t)blockRow * F_DIM;

    // load indices: each thread loads 2 float4 of x and 2 float4 of w per chunk
    const int v0  = tid;
    const int m0  = v0 >> 2;
    const int kq0 = (v0 & 3) << 2;
    const int v1  = tid + 256;
    const int m1  = v1 >> 2;
    const int kq1 = (v1 & 3) << 2;

    float4 pa0, pa1, pb0, pb1;
    // preload chunk 0
    pa0 = *(const float4*)(xblk + (size_t)m0 * F_DIM + kq0);
    pa1 = *(const float4*)(xblk + (size_t)m1 * F_DIM + kq1);
    pb0 = *(const float4*)(w    + (size_t)m0 * F_DIM + kq0);
    pb1 = *(const float4*)(w    + (size_t)m1 * F_DIM + kq1);

    for (int k0 = 0; k0 < F_DIM; k0 += KC) {
        // stage registers -> smem (transposed: [k][m])
        sm[AS_OFF + (kq0 + 0) * 128 + m0] = pa0.x;
        sm[AS_OFF + (kq0 + 1) * 128 + m0] = pa0.y;
        sm[AS_OFF + (kq0 + 2) * 128 + m0] = pa0.z;
        sm[AS_OFF + (kq0 + 3) * 128 + m0] = pa0.w;
        sm[AS_OFF + (kq1 + 0) * 128 + m1] = pa1.x;
        sm[AS_OFF + (kq1 + 1) * 128 + m1] = pa1.y;
        sm[AS_OFF + (kq1 + 2) * 128 + m1] = pa1.z;
        sm[AS_OFF + (kq1 + 3) * 128 + m1] = pa1.w;
        sm[BS_OFF + (kq0 + 0) * 128 + m0] = pb0.x;
        sm[BS_OFF + (kq0 + 1) * 128 + m0] = pb0.y;
        sm[BS_OFF + (kq0 + 2) * 128 + m0] = pb0.z;
        sm[BS_OFF + (kq0 + 3) * 128 + m0] = pb0.w;
        sm[BS_OFF + (kq1 + 0) * 128 + m1] = pb1.x;
        sm[BS_OFF + (kq1 + 1) * 128 + m1] = pb1.y;
        sm[BS_OFF + (kq1 + 2) * 128 + m1] = pb1.z;
        sm[BS_OFF + (kq1 + 3) * 128 + m1] = pb1.w;
        __syncthreads();

        // prefetch next chunk while computing this one
        const int kn = k0 + KC;
        if (kn < F_DIM) {
            pa0 = *(const float4*)(xblk + (size_t)m0 * F_DIM + kn + kq0);
            pa1 = *(const float4*)(xblk + (size_t)m1 * F_DIM + kn + kq1);
            pb0 = *(const float4*)(w    + (size_t)m0 * F_DIM + kn + kq0);
            pb1 = *(const float4*)(w    + (size_t)m1 * F_DIM + kn + kq1);
        }

        #pragma unroll
        for (int k = 0; k < KC; ++k) {
            float a[8], b[8];
            *(float4*)(a)     = *(const float4*)&sm[AS_OFF + k * 128 + ty * 8];
            *(float4*)(a + 4) = *(const float4*)&sm[AS_OFF + k * 128 + ty * 8 + 4];
            *(float4*)(b)     = *(const float4*)&sm[BS_OFF + k * 128 + tx * 8];
            *(float4*)(b + 4) = *(const float4*)&sm[BS_OFF + k * 128 + tx * 8 + 4];
            #pragma unroll
            for (int i = 0; i < 8; ++i)
                #pragma unroll
                for (int j = 0; j < 8; ++j)
                    acc[i][j] = fmaf(a[i], b[j], acc[i][j]);
        }
        __syncthreads();
    }

    // ---------------- Epilogue: si = alpha*exp(-gamma*d), raw tile + row max -
    #pragma unroll
    for (int i = 0; i < 8; ++i) {
        const int m = ty * 8 + i;
        const float xn = sm[XNORM_OFF + m];
        float mx = 0.f;
        #pragma unroll
        for (int j = 0; j < 8; ++j) {
            const int n = tx * 8 + j;
            float d = xn + sm[WNORM_OFF + n] - 2.0f * acc[i][j];
            float vv = sm[ALPHA_OFF + n] * expf(-sm[GAMMA_OFF + n] * d);
            sm[SARR_OFF + m * SARR_STRIDE + n] = vv;   // raw si
            mx = fmaxf(mx, vv);
        }
        sm[RED_OFF + m * 16 + tx] = mx;
    }
    __syncthreads();

    if (tid < 128) {
        float mx = sm[RED_OFF + tid * 16];
        #pragma unroll
        for (int t = 1; t < 16; ++t) mx = fmaxf(mx, sm[RED_OFF + tid * 16 + t]);
        sm[RMAX_OFF + tid] = mx;
    }
    __syncthreads();

    // ---------------- DS combination scan: one thread per row ---------------
    if (tid < 128) {
        const int r = tid;
        const float invm = 1.0f / (sm[RMAX_OFF + r] + 1e-4f);

        float m1v[C_DIM + 1];
        {
            float s0 = sm[SARR_OFF + r * SARR_STRIDE + 0] * invm;
            #pragma unroll
            for (int c = 0; c < C_DIM; ++c) m1v[c] = sm[U_OFF + c * P_DIM + 0] * s0;
            m1v[C_DIM] = 1.0f - s0;
        }

        for (int p = 1; p < P_DIM; ++p) {
            float s  = sm[SARR_OFF + r * SARR_STRIDE + p] * invm;
            float o2 = 1.0f - s;
            float o1 = m1v[C_DIM];
            float cc[C_DIM + 1];
            #pragma unroll
            for (int c = 0; c < C_DIM; ++c) {
                float m2 = sm[U_OFF + c * P_DIM + p] * s;
                cc[c] = m1v[c] * m2 + m1v[c] * o2 + o1 * m2;
            }
            {
                float m2 = o2;   // last component of m2
                cc[C_DIM] = m1v[C_DIM] * m2 + m1v[C_DIM] * o2 + o1 * m2;
            }
            // renormalize every 4 steps (recurrence is scale-invariant; keeps
            // magnitudes away from under/overflow; final exact normalize below)
            if ((p & 3) == 0) {
                float csum = 0.f;
                #pragma unroll
                for (int c = 0; c <= C_DIM; ++c) csum += cc[c];
                float inv = __fdividef(1.0f, csum);
                #pragma unroll
                for (int c = 0; c <= C_DIM; ++c) m1v[c] = cc[c] * inv;
            } else {
                #pragma unroll
                for (int c = 0; c <= C_DIM; ++c) m1v[c] = cc[c];
            }
        }

        float tot = 0.f;
        #pragma unroll
        for (int c = 0; c <= C_DIM; ++c) tot += m1v[c];
        float inv = 1.0f / tot;
        float* op = out + (size_t)(blockRow + r) * (C_DIM + 1);
        #pragma unroll
        for (int c = 0; c <= C_DIM; ++c) op[c] = m1v[c] * inv;
    }
}

extern "C" void kernel_launch(void* const* d_in, const int* in_sizes, int n_in,
                              void* d_out, int out_size)
{
    const float* x    = (const float*)d_in[0];
    const float* w    = (const float*)d_in[1];
    const float* eta  = (const float*)d_in[2];
    const float* xi   = (const float*)d_in[3];
    const float* beta = (const float*)d_in[4];
    float* out = (float*)d_out;

    cudaFuncSetAttribute(ds_fused_kernel,
                         cudaFuncAttributeMaxDynamicSharedMemorySize, SMEM_BYTES);

    ds_fused_kernel<<<B_TOTAL / MT, 256, SMEM_BYTES>>>(x, w, eta, xi, beta, out);
}

// round 3
// speedup vs baseline: 1.7960x; 1.7960x over previous
#include <cuda_runtime.h>
#include <cstdint>
#include <math.h>

#define B_TOTAL 16384
#define F_DIM   512
#define P_DIM   128
#define C_DIM   10
#define MT      128
#define KC      64
#define NCHUNK  8
#define THREADS 512

// bf16 tile rows: 64 elems = 128B + 16B pad -> 144B stride (conflict-free ldmatrix)
#define RS_BY   144
#define TILE_BY (128 * RS_BY)            // 18432 B
#define STAGE_BY (4 * TILE_BY)           // 73728 B
#define AHI_BY  0
#define ALO_BY  TILE_BY
#define BHI_BY  (2 * TILE_BY)
#define BLO_BY  (3 * TILE_BY)

// float-index layout (SARR aliases stage0 after GEMM)
#define SARR_OFF    0
#define SARR_STRIDE 129
#define U_OFF       (2 * STAGE_BY / 4)            // 36864
#define XNORM_OFF   (U_OFF + C_DIM * P_DIM)       // 38144
#define WNORM_OFF   (XNORM_OFF + 128)
#define GAMMA_OFF   (WNORM_OFF + 128)
#define ALPHA_OFF   (GAMMA_OFF + 128)
#define XPART_OFF   (ALPHA_OFF + 128)             // 128*8
#define WPART_OFF   (XPART_OFF + 1024)            // 128*4
#define SMEM_FLOATS (WPART_OFF + 512)
#define SMEM_ALLOC  (SMEM_FLOATS * 4 + 1024)

__device__ __forceinline__ uint32_t smem_u32(const void* p) {
    uint32_t a;
    asm("{ .reg .u64 t; cvta.to.shared.u64 t, %1; cvt.u32.u64 %0, t; }"
        : "=r"(a) : "l"(p));
    return a;
}
__device__ __forceinline__ uint32_t pack_bf16x2(float lo_elem, float hi_elem) {
    uint32_t r;
    asm("cvt.rn.bf16x2.f32 %0, %1, %2;" : "=r"(r) : "f"(hi_elem), "f"(lo_elem));
    return r;
}
#define LDSM4(r, addr) \
    asm volatile("ldmatrix.sync.aligned.m8n8.x4.shared.b16 {%0,%1,%2,%3}, [%4];" \
        : "=r"((r)[0]), "=r"((r)[1]), "=r"((r)[2]), "=r"((r)[3]) : "r"(addr))
#define MMA(acc, a, b0, b1) \
    asm volatile("mma.sync.aligned.m16n8k16.row.col.f32.bf16.bf16.f32 " \
        "{%0,%1,%2,%3}, {%4,%5,%6,%7}, {%8,%9}, {%0,%1,%2,%3};" \
        : "+f"((acc)[0]), "+f"((acc)[1]), "+f"((acc)[2]), "+f"((acc)[3]) \
        : "r"((a)[0]), "r"((a)[1]), "r"((a)[2]), "r"((a)[3]), "r"(b0), "r"(b1))

// convert 8 fp32 -> 8 bf16 hi + 8 bf16 lo (exact residual split); returns sum sq
__device__ __forceinline__ float conv8(const float* __restrict__ src,
                                       char* dhi, char* dlo) {
    float4 v0 = *(const float4*)(src);
    float4 v1 = *(const float4*)(src + 4);
    uint32_t u0 = __float_as_uint(v0.x), u1 = __float_as_uint(v0.y);
    uint32_t u2 = __float_as_uint(v0.z), u3 = __float_as_uint(v0.w);
    uint32_t u4 = __float_as_uint(v1.x), u5 = __float_as_uint(v1.y);
    uint32_t u6 = __float_as_uint(v1.z), u7 = __float_as_uint(v1.w);
    uint4 hi;
    hi.x = __byte_perm(u0, u1, 0x7632);
    hi.y = __byte_perm(u2, u3, 0x7632);
    hi.z = __byte_perm(u4, u5, 0x7632);
    hi.w = __byte_perm(u6, u7, 0x7632);
    uint4 lo;
    lo.x = pack_bf16x2(v0.x - __uint_as_float(u0 & 0xFFFF0000u),
                       v0.y - __uint_as_float(u1 & 0xFFFF0000u));
    lo.y = pack_bf16x2(v0.z - __uint_as_float(u2 & 0xFFFF0000u),
                       v0.w - __uint_as_float(u3 & 0xFFFF0000u));
    lo.z = pack_bf16x2(v1.x - __uint_as_float(u4 & 0xFFFF0000u),
                       v1.y - __uint_as_float(u5 & 0xFFFF0000u));
    lo.w = pack_bf16x2(v1.z - __uint_as_float(u6 & 0xFFFF0000u),
                       v1.w - __uint_as_float(u7 & 0xFFFF0000u));
    *(uint4*)dhi = hi;
    *(uint4*)dlo = lo;
    return v0.x*v0.x + v0.y*v0.y + v0.z*v0.z + v0.w*v0.w
         + v1.x*v1.x + v1.y*v1.y + v1.z*v1.z + v1.w*v1.w;
}

__global__ __launch_bounds__(THREADS, 1)
void ds_mma_kernel(const float* __restrict__ x,
                   const float* __restrict__ w,
                   const float* __restrict__ eta,
                   const float* __restrict__ xi,
                   const float* __restrict__ beta,
                   float* __restrict__ out)
{
    extern __shared__ char dsm[];
    uintptr_t ga = ((uintptr_t)dsm + 1023) & ~(uintptr_t)1023;
    float* smf = (float*)ga;
    char*  smc = (char*)ga;
    const uint32_t sb = smem_u32(smf);

    const int tid  = threadIdx.x;
    const int lane = tid & 31;
    const int wid  = tid >> 5;
    const int wid_m = wid >> 2;     // 0..3
    const int wid_n = wid & 3;      // 0..3
    const int blockRow = blockIdx.x * MT;

    // ---------------- Prologue: per-p params + wnorm partials ----------------
    if (tid < P_DIM) {
        const int p = tid;
        float e = eta[p];
        smf[GAMMA_OFF + p] = e * e;
        smf[ALPHA_OFF + p] = 1.0f / (1.0f + expf(-xi[p]));
        float b2[C_DIM]; float bs = 0.f;
        #pragma unroll
        for (int c = 0; c < C_DIM; ++c) {
            float bv = beta[c * P_DIM + p];
            b2[c] = bv * bv; bs += b2[c];
        }
        float binv = 1.0f / bs;
        #pragma unroll
        for (int c = 0; c < C_DIM; ++c) smf[U_OFF + c * P_DIM + p] = b2[c] * binv;
    }
    {   // wnorm: 4 threads per prototype row (deterministic partials)
        const int p = tid >> 2, q = tid & 3;
        const float4* wr = (const float4*)(w + (size_t)p * F_DIM + q * 128);
        float s0 = 0.f, s1 = 0.f, s2 = 0.f, s3 = 0.f;
        #pragma unroll 8
        for (int i = 0; i < 32; ++i) {
            float4 v = wr[i];
            s0 += v.x * v.x; s1 += v.y * v.y; s2 += v.z * v.z; s3 += v.w * v.w;
        }
        smf[WPART_OFF + p * 4 + q] = (s0 + s1) + (s2 + s3);
    }
    __syncthreads();
    if (tid < 128) {
        float s = smf[WPART_OFF + tid * 4 + 0] + smf[WPART_OFF + tid * 4 + 1]
                + smf[WPART_OFF + tid * 4 + 2] + smf[WPART_OFF + tid * 4 + 3];
        smf[WNORM_OFF + tid] = s;
    }

    // conversion thread mapping: 2 groups of 8 elems; fixed rows per thread
    const int row0 = tid >> 3;            // 0..63  (group1 handles row0+64)
    const int kq   = (tid & 7) << 3;      // 0,8,...,56
    float xn0 = 0.f, xn1 = 0.f;

    // convert chunk 0 -> stage 0
    {
        char* sp = smc;
        const float* sx0 = x + (size_t)(blockRow + row0) * F_DIM + kq;
        xn0 += conv8(sx0, sp + AHI_BY + row0 * RS_BY + kq * 2,
                          sp + ALO_BY + row0 * RS_BY + kq * 2);
        const float* sx1 = x + (size_t)(blockRow + row0 + 64) * F_DIM + kq;
        xn1 += conv8(sx1, sp + AHI_BY + (row0 + 64) * RS_BY + kq * 2,
                          sp + ALO_BY + (row0 + 64) * RS_BY + kq * 2);
        conv8(w + (size_t)row0 * F_DIM + kq,
              sp + BHI_BY + row0 * RS_BY + kq * 2,
              sp + BLO_BY + row0 * RS_BY + kq * 2);
        conv8(w + (size_t)(row0 + 64) * F_DIM + kq,
              sp + BHI_BY + (row0 + 64) * RS_BY + kq * 2,
              sp + BLO_BY + (row0 + 64) * RS_BY + kq * 2);
    }
    __syncthreads();

    // ldmatrix per-lane offsets (bytes within a tile)
    const uint32_t a_off = (uint32_t)((((lane >> 3) & 1) * 8 + (lane & 7)) * RS_BY
                                      + (lane >> 4) * 16);
    const uint32_t b_off = (uint32_t)(((lane >> 4) * 8 + (lane & 7)) * RS_BY
                                      + ((lane >> 3) & 1) * 16);
    const uint32_t a_row_by = (uint32_t)(wid_m * 32) * RS_BY;
    const uint32_t b_row_by = (uint32_t)(wid_n * 32) * RS_BY;

    float acc[2][4][4];
    #pragma unroll
    for (int i = 0; i < 2; ++i)
        #pragma unroll
        for (int j = 0; j < 4; ++j)
            #pragma unroll
            for (int k = 0; k < 4; ++k) acc[i][j][k] = 0.f;

    #pragma unroll 1
    for (int c = 0; c < NCHUNK; ++c) {
        const int cur = c & 1;

        // ---- convert next chunk into other stage (gmem loads issued first) --
        if (c < NCHUNK - 1) {
            const int kb = (c + 1) * KC;
            char* sp = smc + (cur ^ 1) * STAGE_BY;
            const float* sx0 = x + (size_t)(blockRow + row0) * F_DIM + kb + kq;
            xn0 += conv8(sx0, sp + AHI_BY + row0 * RS_BY + kq * 2,
                              sp + ALO_BY + row0 * RS_BY + kq * 2);
            const float* sx1 = x + (size_t)(blockRow + row0 + 64) * F_DIM + kb + kq;
            xn1 += conv8(sx1, sp + AHI_BY + (row0 + 64) * RS_BY + kq * 2,
                              sp + ALO_BY + (row0 + 64) * RS_BY + kq * 2);
            conv8(w + (size_t)row0 * F_DIM + kb + kq,
                  sp + BHI_BY + row0 * RS_BY + kq * 2,
                  sp + BLO_BY + row0 * RS_BY + kq * 2);
            conv8(w + (size_t)(row0 + 64) * F_DIM + kb + kq,
                  sp + BHI_BY + (row0 + 64) * RS_BY + kq * 2,
                  sp + BLO_BY + (row0 + 64) * RS_BY + kq * 2);
        }

        // ---- MMA over current stage: 4 k16 steps x 3 split terms ----
        const uint32_t sbase = sb + cur * STAGE_BY;
        #pragma unroll
        for (int ks = 0; ks < 4; ++ks) {
            const uint32_t kby = ks * 32;
            uint32_t ahi[2][4], alo[2][4], bhi[2][4], blo[2][4];
            #pragma unroll
            for (int mb = 0; mb < 2; ++mb) {
                uint32_t base = sbase + a_row_by + mb * 16 * RS_BY + kby + a_off;
                LDSM4(ahi[mb], base + AHI_BY);
                LDSM4(alo[mb], base + ALO_BY);
            }
            #pragma unroll
            for (int nb = 0; nb < 2; ++nb) {
                uint32_t base = sbase + b_row_by + nb * 16 * RS_BY + kby + b_off;
                LDSM4(bhi[nb], base + BHI_BY);
                LDSM4(blo[nb], base + BLO_BY);
            }
            #pragma unroll
            for (int mb = 0; mb < 2; ++mb) {
                #pragma unroll
                for (int nf = 0; nf < 4; ++nf) {
                    const int nb = nf >> 1, h = (nf & 1) << 1;
                    MMA(acc[mb][nf], ahi[mb], bhi[nb][h], bhi[nb][h + 1]);
                    MMA(acc[mb][nf], ahi[mb], blo[nb][h], blo[nb][h + 1]);
                    MMA(acc[mb][nf], alo[mb], bhi[nb][h], bhi[nb][h + 1]);
                }
            }
        }
        __syncthreads();
    }

    // ---------------- finalize xnorm (deterministic tree) -------------------
    smf[XPART_OFF + row0 * 8 + (tid & 7)] = xn0;
    smf[XPART_OFF + (row0 + 64) * 8 + (tid & 7)] = xn1;
    __syncthreads();
    if (tid < 128) {
        float s = 0.f;
        #pragma unroll
        for (int q = 0; q < 8; ++q) s += smf[XPART_OFF + tid * 8 + q];
        smf[XNORM_OFF + tid] = s;
    }
    __syncthreads();

    // ---------------- Epilogue: si from accum fragments -> SARR -------------
    #pragma unroll
    for (int mb = 0; mb < 2; ++mb) {
        const int rA = wid_m * 32 + mb * 16 + (lane >> 2);
        const float xnA = smf[XNORM_OFF + rA];
        const float xnB = smf[XNORM_OFF + rA + 8];
        #pragma unroll
        for (int nf = 0; nf < 4; ++nf) {
            const int cl = wid_n * 32 + nf * 8 + ((lane & 3) << 1);
            const float wn0 = smf[WNORM_OFF + cl], wn1 = smf[WNORM_OFF + cl + 1];
            const float g0 = smf[GAMMA_OFF + cl], g1 = smf[GAMMA_OFF + cl + 1];
            const float al0 = smf[ALPHA_OFF + cl], al1 = smf[ALPHA_OFF + cl + 1];
            float d00 = xnA + wn0 - 2.0f * acc[mb][nf][0];
            float d01 = xnA + wn1 - 2.0f * acc[mb][nf][1];
            float d10 = xnB + wn0 - 2.0f * acc[mb][nf][2];
            float d11 = xnB + wn1 - 2.0f * acc[mb][nf][3];
            smf[SARR_OFF + rA * SARR_STRIDE + cl]           = al0 * __expf(-g0 * d00);
            smf[SARR_OFF + rA * SARR_STRIDE + cl + 1]       = al1 * __expf(-g1 * d01);
            smf[SARR_OFF + (rA + 8) * SARR_STRIDE + cl]     = al0 * __expf(-g0 * d10);
            smf[SARR_OFF + (rA + 8) * SARR_STRIDE + cl + 1] = al1 * __expf(-g1 * d11);
        }
    }
    __syncthreads();

    // ---------------- DS combination scan (one thread per row) --------------
    if (tid < 128) {
        const int r = tid;
        float mx = 0.f;
        #pragma unroll 8
        for (int p = 0; p < P_DIM; ++p)
            mx = fmaxf(mx, smf[SARR_OFF + r * SARR_STRIDE + p]);
        const float invm = 1.0f / (mx + 1e-4f);

        float m1v[C_DIM + 1];
        {
            float s0 = smf[SARR_OFF + r * SARR_STRIDE + 0] * invm;
            #pragma unroll
            for (int c = 0; c < C_DIM; ++c) m1v[c] = smf[U_OFF + c * P_DIM + 0] * s0;
            m1v[C_DIM] = 1.0f - s0;
        }
        for (int p = 1; p < P_DIM; ++p) {
            float s  = smf[SARR_OFF + r * SARR_STRIDE + p] * invm;
            float o2 = 1.0f - s;
            float o1 = m1v[C_DIM];
            float cc[C_DIM + 1];
            #pragma unroll
            for (int c = 0; c < C_DIM; ++c) {
                float m2 = smf[U_OFF + c * P_DIM + p] * s;
                cc[c] = m1v[c] * m2 + m1v[c] * o2 + o1 * m2;
            }
            {
                float m2 = o2;
                cc[C_DIM] = m1v[C_DIM] * m2 + m1v[C_DIM] * o2 + o1 * m2;
            }
            if ((p & 3) == 0) {
                float csum = 0.f;
                #pragma unroll
                for (int c = 0; c <= C_DIM; ++c) csum += cc[c];
                float inv = __fdividef(1.0f, csum);
                #pragma unroll
                for (int c = 0; c <= C_DIM; ++c) m1v[c] = cc[c] * inv;
            } else {
                #pragma unroll
                for (int c = 0; c <= C_DIM; ++c) m1v[c] = cc[c];
            }
        }
        float tot = 0.f;
        #pragma unroll
        for (int c = 0; c <= C_DIM; ++c) tot += m1v[c];
        float inv = 1.0f / tot;
        float* op = out + (size_t)(blockRow + r) * (C_DIM + 1);
        #pragma unroll
        for (int c = 0; c <= C_DIM; ++c) op[c] = m1v[c] * inv;
    }
}

extern "C" void kernel_launch(void* const* d_in, const int* in_sizes, int n_in,
                              void* d_out, int out_size)
{
    const float* x    = (const float*)d_in[0];
    const float* w    = (const float*)d_in[1];
    const float* eta  = (const float*)d_in[2];
    const float* xi   = (const float*)d_in[3];
    const float* beta = (const float*)d_in[4];
    float* out = (float*)d_out;

    cudaFuncSetAttribute(ds_mma_kernel,
                         cudaFuncAttributeMaxDynamicSharedMemorySize, SMEM_ALLOC);
    ds_mma_kernel<<<B_TOTAL / MT, THREADS, SMEM_ALLOC>>>(x, w, eta, xi, beta, out);
}

// round 4
// speedup vs baseline: 2.1605x; 1.2029x over previous
#include <cuda_runtime.h>
#include <cuda_bf16.h>
#include <cstdint>
#include <math.h>

#define B_TOTAL 16384
#define F_DIM   512
#define P_DIM   128
#define C_DIM   10
#define MT      128
#define KC      64
#define NCHUNK  8
#define THREADS 512

// bf16 tile rows: 64 elems = 128B + 16B pad -> 144B stride (conflict-free ldmatrix)
#define RS_BY   144
#define TILE_BY (128 * RS_BY)            // 18432 B
#define STAGE_BY (4 * TILE_BY)           // 73728 B
#define AHI_BY  0
#define ALO_BY  TILE_BY
#define BHI_BY  (2 * TILE_BY)
#define BLO_BY  (3 * TILE_BY)

#define SARR_OFF    0
#define SARR_STRIDE 129
#define U_OFF       (2 * STAGE_BY / 4)            // 36864 floats (after stages)
#define XNORM_OFF   (U_OFF + C_DIM * P_DIM)
#define WNORM_OFF   (XNORM_OFF + 128)
#define GAMMA_OFF   (WNORM_OFF + 128)
#define ALPHA_OFF   (GAMMA_OFF + 128)
#define XPART_OFF   (ALPHA_OFF + 128)
#define SMEM_FLOATS (XPART_OFF + 1024)
#define SMEM_ALLOC  (SMEM_FLOATS * 4 + 1024)

// w chunk tile: 128 rows x 64 bf16 = 16384 B
#define WCH_BY 16384

__device__ __align__(256) __nv_bfloat16 g_whi[NCHUNK * P_DIM * KC];
__device__ __align__(256) __nv_bfloat16 g_wlo[NCHUNK * P_DIM * KC];
__device__ float g_params[384 + C_DIM * P_DIM];   // wnorm|gamma|alpha|u

__device__ __forceinline__ uint32_t smem_u32(const void* p) {
    uint32_t a;
    asm("{ .reg .u64 t; cvta.to.shared.u64 t, %1; cvt.u32.u64 %0, t; }"
        : "=r"(a) : "l"(p));
    return a;
}
__device__ __forceinline__ uint32_t pack_bf16x2(float lo_elem, float hi_elem) {
    uint32_t r;
    asm("cvt.rn.bf16x2.f32 %0, %1, %2;" : "=r"(r) : "f"(hi_elem), "f"(lo_elem));
    return r;
}
#define LDSM4(r, addr) \
    asm volatile("ldmatrix.sync.aligned.m8n8.x4.shared.b16 {%0,%1,%2,%3}, [%4];" \
        : "=r"((r)[0]), "=r"((r)[1]), "=r"((r)[2]), "=r"((r)[3]) : "r"(addr))
#define MMA(acc, a, b0, b1) \
    asm volatile("mma.sync.aligned.m16n8k16.row.col.f32.bf16.bf16.f32 " \
        "{%0,%1,%2,%3}, {%4,%5,%6,%7}, {%8,%9}, {%0,%1,%2,%3};" \
        : "+f"((acc)[0]), "+f"((acc)[1]), "+f"((acc)[2]), "+f"((acc)[3]) \
        : "r"((a)[0]), "r"((a)[1]), "r"((a)[2]), "r"((a)[3]), "r"(b0), "r"(b1))
#define CPA16(dst, src) \
    asm volatile("cp.async.cg.shared.global [%0], [%1], 16;" :: "r"(dst), "l"(src) : "memory")
#define CP_COMMIT() asm volatile("cp.async.commit_group;" ::: "memory")
#define CP_WAIT0()  asm volatile("cp.async.wait_group 0;" ::: "memory")

// convert 8 fp32 (in regs) -> 8 bf16 hi + 8 bf16 lo; returns sum of squares
__device__ __forceinline__ float conv8r(float4 v0, float4 v1, char* dhi, char* dlo) {
    uint32_t u0 = __float_as_uint(v0.x), u1 = __float_as_uint(v0.y);
    uint32_t u2 = __float_as_uint(v0.z), u3 = __float_as_uint(v0.w);
    uint32_t u4 = __float_as_uint(v1.x), u5 = __float_as_uint(v1.y);
    uint32_t u6 = __float_as_uint(v1.z), u7 = __float_as_uint(v1.w);
    uint4 hi;
    hi.x = __byte_perm(u0, u1, 0x7632);
    hi.y = __byte_perm(u2, u3, 0x7632);
    hi.z = __byte_perm(u4, u5, 0x7632);
    hi.w = __byte_perm(u6, u7, 0x7632);
    uint4 lo;
    lo.x = pack_bf16x2(v0.x - __uint_as_float(u0 & 0xFFFF0000u),
                       v0.y - __uint_as_float(u1 & 0xFFFF0000u));
    lo.y = pack_bf16x2(v0.z - __uint_as_float(u2 & 0xFFFF0000u),
                       v0.w - __uint_as_float(u3 & 0xFFFF0000u));
    lo.z = pack_bf16x2(v1.x - __uint_as_float(u4 & 0xFFFF0000u),
                       v1.y - __uint_as_float(u5 & 0xFFFF0000u));
    lo.w = pack_bf16x2(v1.z - __uint_as_float(u6 & 0xFFFF0000u),
                       v1.w - __uint_as_float(u7 & 0xFFFF0000u));
    *(uint4*)dhi = hi;
    *(uint4*)dlo = lo;
    return v0.x*v0.x + v0.y*v0.y + v0.z*v0.z + v0.w*v0.w
         + v1.x*v1.x + v1.y*v1.y + v1.z*v1.z + v1.w*v1.w;
}

// ------------------------- prep kernel: w split + params --------------------
__global__ __launch_bounds__(128)
void prep_kernel(const float* __restrict__ w,
                 const float* __restrict__ eta,
                 const float* __restrict__ xi,
                 const float* __restrict__ beta)
{
    __shared__ float sred[128];
    const int p = blockIdx.x;
    const int t = threadIdx.x;
    float4 v = ((const float4*)(w + (size_t)p * F_DIM))[t];
    uint32_t u0 = __float_as_uint(v.x), u1 = __float_as_uint(v.y);
    uint32_t u2 = __float_as_uint(v.z), u3 = __float_as_uint(v.w);
    uint32_t h0 = __byte_perm(u0, u1, 0x7632);
    uint32_t h1 = __byte_perm(u2, u3, 0x7632);
    uint32_t l0 = pack_bf16x2(v.x - __uint_as_float(u0 & 0xFFFF0000u),
                              v.y - __uint_as_float(u1 & 0xFFFF0000u));
    uint32_t l1 = pack_bf16x2(v.z - __uint_as_float(u2 & 0xFFFF0000u),
                              v.w - __uint_as_float(u3 & 0xFFFF0000u));
    const int c = t >> 4;            // chunk
    const int k = (t & 15) << 2;     // k within chunk
    const int idx = c * (P_DIM * KC) + p * KC + k;
    *(uint2*)&g_whi[idx] = make_uint2(h0, h1);
    *(uint2*)&g_wlo[idx] = make_uint2(l0, l1);

    sred[t] = v.x*v.x + v.y*v.y + v.z*v.z + v.w*v.w;
    __syncthreads();
    #pragma unroll
    for (int o = 64; o > 0; o >>= 1) {
        if (t < o) sred[t] += sred[t + o];
        __syncthreads();
    }
    if (t == 0) {
        g_params[p] = sred[0];                       // wnorm
        float e = eta[p];
        g_params[128 + p] = e * e;                   // gamma
        g_params[256 + p] = 1.0f / (1.0f + expf(-xi[p]));  // alpha
        float b2[C_DIM]; float bs = 0.f;
        #pragma unroll
        for (int cc = 0; cc < C_DIM; ++cc) {
            float bv = beta[cc * P_DIM + p];
            b2[cc] = bv * bv; bs += b2[cc];
        }
        float binv = 1.0f / bs;
        #pragma unroll
        for (int cc = 0; cc < C_DIM; ++cc)
            g_params[384 + cc * P_DIM + p] = b2[cc] * binv;
    }
}

// ------------------------------- main kernel --------------------------------
__global__ __launch_bounds__(THREADS, 1)
void ds_mma_kernel(const float* __restrict__ x,
                   float* __restrict__ out)
{
    extern __shared__ char dsm[];
    uintptr_t ga = ((uintptr_t)dsm + 1023) & ~(uintptr_t)1023;
    float* smf = (float*)ga;
    char*  smc = (char*)ga;
    const uint32_t sb = smem_u32(smf);

    const int tid  = threadIdx.x;
    const int lane = tid & 31;
    const int wid  = tid >> 5;
    const int wid_m = wid >> 2;
    const int wid_n = wid & 3;
    const int blockRow = blockIdx.x * MT;

    // load precomputed params into smem
    #pragma unroll
    for (int i = tid; i < 384; i += THREADS) smf[WNORM_OFF + i] = g_params[i];
    #pragma unroll
    for (int i = tid; i < C_DIM * P_DIM; i += THREADS) smf[U_OFF + i] = g_params[384 + i];

    // conversion mapping: thread handles rows r0 and r0+64 at k-offset kq
    const int r0 = tid >> 3;
    const int kq = (tid & 7) << 3;
    const float* xrow0 = x + (size_t)(blockRow + r0) * F_DIM + kq;
    const float* xrow1 = x + (size_t)(blockRow + r0 + 64) * F_DIM + kq;
    float xn0 = 0.f, xn1 = 0.f;

    // B copy: 4x16B per thread; o=0,1 -> hi tile, o=2,3 -> lo tile
    const int bslot0 = tid;          // within-tile 16B slot for o=0 (hi)
    // slot s: row = s>>3, col16 = s&7

    // ---- prologue: chunk 0 into stage 0 ----
    {
        const char* shi = (const char*)g_whi;       // chunk 0
        const char* slo = (const char*)g_wlo;
        #pragma unroll
        for (int o = 0; o < 2; ++o) {
            int s = bslot0 + o * 512;
            uint32_t dst = sb + BHI_BY + (uint32_t)(s >> 3) * RS_BY + (uint32_t)(s & 7) * 16;
            CPA16(dst, shi + s * 16);
        }
        #pragma unroll
        for (int o = 0; o < 2; ++o) {
            int s = bslot0 + o * 512;
            uint32_t dst = sb + BLO_BY + (uint32_t)(s >> 3) * RS_BY + (uint32_t)(s & 7) * 16;
            CPA16(dst, slo + s * 16);
        }
        CP_COMMIT();
        float4 a0 = *(const float4*)(xrow0);
        float4 a1 = *(const float4*)(xrow0 + 4);
        float4 a2 = *(const float4*)(xrow1);
        float4 a3 = *(const float4*)(xrow1 + 4);
        xn0 += conv8r(a0, a1, smc + AHI_BY + r0 * RS_BY + kq * 2,
                              smc + ALO_BY + r0 * RS_BY + kq * 2);
        xn1 += conv8r(a2, a3, smc + AHI_BY + (r0 + 64) * RS_BY + kq * 2,
                              smc + ALO_BY + (r0 + 64) * RS_BY + kq * 2);
        CP_WAIT0();
    }
    __syncthreads();

    const uint32_t a_off = (uint32_t)((((lane >> 3) & 1) * 8 + (lane & 7)) * RS_BY
                                      + (lane >> 4) * 16);
    const uint32_t b_off = (uint32_t)(((lane >> 4) * 8 + (lane & 7)) * RS_BY
                                      + ((lane >> 3) & 1) * 16);
    const uint32_t a_row_by = (uint32_t)(wid_m * 32) * RS_BY;
    const uint32_t b_row_by = (uint32_t)(wid_n * 32) * RS_BY;

    float acc[2][4][4];
    #pragma unroll
    for (int i = 0; i < 2; ++i)
        #pragma unroll
        for (int j = 0; j < 4; ++j)
            #pragma unroll
            for (int k = 0; k < 4; ++k) acc[i][j][k] = 0.f;

    float4 pA0, pA1, pA2, pA3;

    #pragma unroll 1
    for (int c = 0; c < NCHUNK; ++c) {
        const int cur = c & 1;
        const uint32_t nbase = sb + (cur ^ 1) * STAGE_BY;

        // ---- issue async loads for chunk c+1 BEFORE the MMA section ----
        if (c < NCHUNK - 1) {
            const char* shi = (const char*)g_whi + (c + 1) * WCH_BY;
            const char* slo = (const char*)g_wlo + (c + 1) * WCH_BY;
            #pragma unroll
            for (int o = 0; o < 2; ++o) {
                int s = bslot0 + o * 512;
                uint32_t dst = nbase + BHI_BY + (uint32_t)(s >> 3) * RS_BY + (uint32_t)(s & 7) * 16;
                CPA16(dst, shi + s * 16);
            }
            #pragma unroll
            for (int o = 0; o < 2; ++o) {
                int s = bslot0 + o * 512;
                uint32_t dst = nbase + BLO_BY + (uint32_t)(s >> 3) * RS_BY + (uint32_t)(s & 7) * 16;
                CPA16(dst, slo + s * 16);
            }
            CP_COMMIT();
            const int kb = (c + 1) * KC;
            pA0 = *(const float4*)(xrow0 + kb);
            pA1 = *(const float4*)(xrow0 + kb + 4);
            pA2 = *(const float4*)(xrow1 + kb);
            pA3 = *(const float4*)(xrow1 + kb + 4);
        }

        // ---- MMA over current stage ----
        const uint32_t sbase = sb + cur * STAGE_BY;
        #pragma unroll
        for (int ks = 0; ks < 4; ++ks) {
            const uint32_t kby = ks * 32;
            uint32_t ahi[2][4], alo[2][4], bhi[2][4], blo[2][4];
            #pragma unroll
            for (int mb = 0; mb < 2; ++mb) {
                uint32_t base = sbase + a_row_by + mb * 16 * RS_BY + kby + a_off;
                LDSM4(ahi[mb], base + AHI_BY);
                LDSM4(alo[mb], base + ALO_BY);
            }
            #pragma unroll
            for (int nb = 0; nb < 2; ++nb) {
                uint32_t base = sbase + b_row_by + nb * 16 * RS_BY + kby + b_off;
                LDSM4(bhi[nb], base + BHI_BY);
                LDSM4(blo[nb], base + BLO_BY);
            }
            #pragma unroll
            for (int mb = 0; mb < 2; ++mb) {
                #pragma unroll
                for (int nf = 0; nf < 4; ++nf) {
                    const int nb = nf >> 1, h = (nf & 1) << 1;
                    MMA(acc[mb][nf], ahi[mb], bhi[nb][h], bhi[nb][h + 1]);
                    MMA(acc[mb][nf], ahi[mb], blo[nb][h], blo[nb][h + 1]);
                    MMA(acc[mb][nf], alo[mb], bhi[nb][h], bhi[nb][h + 1]);
                }
            }
        }

        // ---- convert prefetched A into next stage (after MMA; LDGs overlapped)
        if (c < NCHUNK - 1) {
            char* np = smc + (cur ^ 1) * STAGE_BY;
            xn0 += conv8r(pA0, pA1, np + AHI_BY + r0 * RS_BY + kq * 2,
                                    np + ALO_BY + r0 * RS_BY + kq * 2);
            xn1 += conv8r(pA2, pA3, np + AHI_BY + (r0 + 64) * RS_BY + kq * 2,
                                    np + ALO_BY + (r0 + 64) * RS_BY + kq * 2);
        }
        CP_WAIT0();
        __syncthreads();
    }

    // ---------------- finalize xnorm (deterministic tree) -------------------
    smf[XPART_OFF + r0 * 8 + (tid & 7)] = xn0;
    smf[XPART_OFF + (r0 + 64) * 8 + (tid & 7)] = xn1;
    __syncthreads();
    if (tid < 128) {
        float s = 0.f;
        #pragma unroll
        for (int q = 0; q < 8; ++q) s += smf[XPART_OFF + tid * 8 + q];
        smf[XNORM_OFF + tid] = s;
    }
    __syncthreads();

    // ---------------- Epilogue: si from accum fragments -> SARR -------------
    #pragma unroll
    for (int mb = 0; mb < 2; ++mb) {
        const int rA = wid_m * 32 + mb * 16 + (lane >> 2);
        const float xnA = smf[XNORM_OFF + rA];
        const float xnB = smf[XNORM_OFF + rA + 8];
        #pragma unroll
        for (int nf = 0; nf < 4; ++nf) {
            const int cl = wid_n * 32 + nf * 8 + ((lane & 3) << 1);
            const float wn0 = smf[WNORM_OFF + cl], wn1 = smf[WNORM_OFF + cl + 1];
            const float g0 = smf[GAMMA_OFF + cl], g1 = smf[GAMMA_OFF + cl + 1];
            const float al0 = smf[ALPHA_OFF + cl], al1 = smf[ALPHA_OFF + cl + 1];
            float d00 = xnA + wn0 - 2.0f * acc[mb][nf][0];
            float d01 = xnA + wn1 - 2.0f * acc[mb][nf][1];
            float d10 = xnB + wn0 - 2.0f * acc[mb][nf][2];
            float d11 = xnB + wn1 - 2.0f * acc[mb][nf][3];
            smf[SARR_OFF + rA * SARR_STRIDE + cl]           = al0 * __expf(-g0 * d00);
            smf[SARR_OFF + rA * SARR_STRIDE + cl + 1]       = al1 * __expf(-g1 * d01);
            smf[SARR_OFF + (rA + 8) * SARR_STRIDE + cl]     = al0 * __expf(-g0 * d10);
            smf[SARR_OFF + (rA + 8) * SARR_STRIDE + cl + 1] = al1 * __expf(-g1 * d11);
        }
    }
    __syncthreads();

    // ---------------- DS combination scan (one thread per row) --------------
    if (tid < 128) {
        const int r = tid;
        float mx = 0.f;
        #pragma unroll 8
        for (int p = 0; p < P_DIM; ++p)
            mx = fmaxf(mx, smf[SARR_OFF + r * SARR_STRIDE + p]);
        const float invm = 1.0f / (mx + 1e-4f);

        float m1v[C_DIM + 1];
        {
            float s0 = smf[SARR_OFF + r * SARR_STRIDE + 0] * invm;
            #pragma unroll
            for (int c = 0; c < C_DIM; ++c) m1v[c] = smf[U_OFF + c * P_DIM + 0] * s0;
            m1v[C_DIM] = 1.0f - s0;
        }
        for (int p = 1; p < P_DIM; ++p) {
            float s  = smf[SARR_OFF + r * SARR_STRIDE + p] * invm;
            float o2 = 1.0f - s;
            float o1 = m1v[C_DIM];
            float cc[C_DIM + 1];
            #pragma unroll
            for (int c = 0; c < C_DIM; ++c) {
                float m2 = smf[U_OFF + c * P_DIM + p] * s;
                cc[c] = m1v[c] * m2 + m1v[c] * o2 + o1 * m2;
            }
            {
                float m2 = o2;
                cc[C_DIM] = m1v[C_DIM] * m2 + m1v[C_DIM] * o2 + o1 * m2;
            }
            if ((p & 3) == 0) {
                float csum = 0.f;
                #pragma unroll
                for (int c = 0; c <= C_DIM; ++c) csum += cc[c];
                float inv = __fdividef(1.0f, csum);
                #pragma unroll
                for (int c = 0; c <= C_DIM; ++c) m1v[c] = cc[c] * inv;
            } else {
                #pragma unroll
                for (int c = 0; c <= C_DIM; ++c) m1v[c] = cc[c];
            }
        }
        float tot = 0.f;
        #pragma unroll
        for (int c = 0; c <= C_DIM; ++c) tot += m1v[c];
        float inv = 1.0f / tot;
        float* op = out + (size_t)(blockRow + r) * (C_DIM + 1);
        #pragma unroll
        for (int c = 0; c <= C_DIM; ++c) op[c] = m1v[c] * inv;
    }
}

extern "C" void kernel_launch(void* const* d_in, const int* in_sizes, int n_in,
                              void* d_out, int out_size)
{
    const float* x    = (const float*)d_in[0];
    const float* w    = (const float*)d_in[1];
    const float* eta  = (const float*)d_in[2];
    const float* xi   = (const float*)d_in[3];
    const float* beta = (const float*)d_in[4];
    float* out = (float*)d_out;

    prep_kernel<<<128, 128>>>(w, eta, xi, beta);

    cudaFuncSetAttribute(ds_mma_kernel,
                         cudaFuncAttributeMaxDynamicSharedMemorySize, SMEM_ALLOC);
    ds_mma_kernel<<<B_TOTAL / MT, THREADS, SMEM_ALLOC>>>(x, out);
}

// round 5
// speedup vs baseline: 2.3973x; 1.1096x over previous
#include <cuda_runtime.h>
#include <cuda_bf16.h>
#include <cstdint>
#include <math.h>

#define B_TOTAL 16384
#define F_DIM   512
#define P_DIM   128
#define C_DIM   10
#define MT      128
#define KC      64
#define NCHUNK  8
#define THREADS 512

// bf16 tile rows: 64 elems = 128B + 16B pad -> 144B stride (conflict-free ldmatrix)
#define RS_BY   144
#define TILE_BY (128 * RS_BY)            // 18432 B
#define STAGE_BY (3 * TILE_BY)           // 55296 B : AHI | BHI | BLO
#define AHI_BY  0
#define BHI_BY  TILE_BY
#define BLO_BY  (2 * TILE_BY)

#define SARR_OFF    0
#define SARR_STRIDE 129
#define U_OFF       (2 * STAGE_BY / 4)            // 27648 floats (after 2 stages)
#define XNORM_OFF   (U_OFF + C_DIM * P_DIM)
#define WNORM_OFF   (XNORM_OFF + 128)
#define GAMMA_OFF   (WNORM_OFF + 128)
#define ALPHA_OFF   (GAMMA_OFF + 128)
#define XPART_OFF   (ALPHA_OFF + 128)
#define SMEM_FLOATS (XPART_OFF + 1024)
#define SMEM_ALLOC  (SMEM_FLOATS * 4 + 1024)

// w chunk tile: 128 rows x 64 bf16 = 16384 B
#define WCH_BY 16384

__device__ __align__(256) __nv_bfloat16 g_whi[NCHUNK * P_DIM * KC];
__device__ __align__(256) __nv_bfloat16 g_wlo[NCHUNK * P_DIM * KC];
__device__ float g_params[384 + C_DIM * P_DIM];   // wnorm|gamma|alpha|u

__device__ __forceinline__ uint32_t smem_u32(const void* p) {
    uint32_t a;
    asm("{ .reg .u64 t; cvta.to.shared.u64 t, %1; cvt.u32.u64 %0, t; }"
        : "=r"(a) : "l"(p));
    return a;
}
__device__ __forceinline__ uint32_t pack_bf16x2(float lo_elem, float hi_elem) {
    uint32_t r;   // d[31:16] = rn(hi_elem), d[15:0] = rn(lo_elem)
    asm("cvt.rn.bf16x2.f32 %0, %1, %2;" : "=r"(r) : "f"(hi_elem), "f"(lo_elem));
    return r;
}
#define LDSM4(r, addr) \
    asm volatile("ldmatrix.sync.aligned.m8n8.x4.shared.b16 {%0,%1,%2,%3}, [%4];" \
        : "=r"((r)[0]), "=r"((r)[1]), "=r"((r)[2]), "=r"((r)[3]) : "r"(addr))
#define MMA(acc, a, b0, b1) \
    asm volatile("mma.sync.aligned.m16n8k16.row.col.f32.bf16.bf16.f32 " \
        "{%0,%1,%2,%3}, {%4,%5,%6,%7}, {%8,%9}, {%0,%1,%2,%3};" \
        : "+f"((acc)[0]), "+f"((acc)[1]), "+f"((acc)[2]), "+f"((acc)[3]) \
        : "r"((a)[0]), "r"((a)[1]), "r"((a)[2]), "r"((a)[3]), "r"(b0), "r"(b1))
#define CPA16(dst, src) \
    asm volatile("cp.async.cg.shared.global [%0], [%1], 16;" :: "r"(dst), "l"(src) : "memory")
#define CP_COMMIT() asm volatile("cp.async.commit_group;" ::: "memory")
#define CP_WAIT0()  asm volatile("cp.async.wait_group 0;" ::: "memory")

// convert 8 fp32 (regs) -> 8 bf16 (RN) into dhi; returns sum of squares (fp32)
__device__ __forceinline__ float conv8h(float4 v0, float4 v1, char* dhi) {
    uint4 hi;
    hi.x = pack_bf16x2(v0.x, v0.y);
    hi.y = pack_bf16x2(v0.z, v0.w);
    hi.z = pack_bf16x2(v1.x, v1.y);
    hi.w = pack_bf16x2(v1.z, v1.w);
    *(uint4*)dhi = hi;
    return v0.x*v0.x + v0.y*v0.y + v0.z*v0.z + v0.w*v0.w
         + v1.x*v1.x + v1.y*v1.y + v1.z*v1.z + v1.w*v1.w;
}

// ------------------------- prep kernel: w split + params --------------------
__global__ __launch_bounds__(128)
void prep_kernel(const float* __restrict__ w,
                 const float* __restrict__ eta,
                 const float* __restrict__ xi,
                 const float* __restrict__ beta)
{
    __shared__ float sred[128];
    const int p = blockIdx.x;
    const int t = threadIdx.x;
    float4 v = ((const float4*)(w + (size_t)p * F_DIM))[t];
    uint32_t u0 = __float_as_uint(v.x), u1 = __float_as_uint(v.y);
    uint32_t u2 = __float_as_uint(v.z), u3 = __float_as_uint(v.w);
    uint32_t h0 = __byte_perm(u0, u1, 0x7632);
    uint32_t h1 = __byte_perm(u2, u3, 0x7632);
    uint32_t l0 = pack_bf16x2(v.x - __uint_as_float(u0 & 0xFFFF0000u),
                              v.y - __uint_as_float(u1 & 0xFFFF0000u));
    uint32_t l1 = pack_bf16x2(v.z - __uint_as_float(u2 & 0xFFFF0000u),
                              v.w - __uint_as_float(u3 & 0xFFFF0000u));
    const int c = t >> 4;            // chunk
    const int k = (t & 15) << 2;     // k within chunk
    const int idx = c * (P_DIM * KC) + p * KC + k;
    *(uint2*)&g_whi[idx] = make_uint2(h0, h1);
    *(uint2*)&g_wlo[idx] = make_uint2(l0, l1);

    sred[t] = v.x*v.x + v.y*v.y + v.z*v.z + v.w*v.w;
    __syncthreads();
    #pragma unroll
    for (int o = 64; o > 0; o >>= 1) {
        if (t < o) sred[t] += sred[t + o];
        __syncthreads();
    }
    if (t == 0) {
        g_params[p] = sred[0];
        float e = eta[p];
        g_params[128 + p] = e * e;
        g_params[256 + p] = 1.0f / (1.0f + expf(-xi[p]));
        float b2[C_DIM]; float bs = 0.f;
        #pragma unroll
        for (int cc = 0; cc < C_DIM; ++cc) {
            float bv = beta[cc * P_DIM + p];
            b2[cc] = bv * bv; bs += b2[cc];
        }
        float binv = 1.0f / bs;
        #pragma unroll
        for (int cc = 0; cc < C_DIM; ++cc)
            g_params[384 + cc * P_DIM + p] = b2[cc] * binv;
    }
}

// ------------------------------- main kernel --------------------------------
__global__ __launch_bounds__(THREADS, 1)
void ds_mma_kernel(const float* __restrict__ x,
                   float* __restrict__ out)
{
    extern __shared__ char dsm[];
    uintptr_t ga = ((uintptr_t)dsm + 1023) & ~(uintptr_t)1023;
    float* smf = (float*)ga;
    char*  smc = (char*)ga;
    const uint32_t sb = smem_u32(smf);

    const int tid  = threadIdx.x;
    const int lane = tid & 31;
    const int wid  = tid >> 5;
    const int wid_m = wid >> 2;
    const int wid_n = wid & 3;
    const int blockRow = blockIdx.x * MT;

    // params -> smem
    #pragma unroll
    for (int i = tid; i < 384; i += THREADS) smf[WNORM_OFF + i] = g_params[i];
    #pragma unroll
    for (int i = tid; i < C_DIM * P_DIM; i += THREADS) smf[U_OFF + i] = g_params[384 + i];

    // x conversion mapping: thread handles rows r0 and r0+64 at k-offset kq
    const int r0 = tid >> 3;
    const int kq = (tid & 7) << 3;
    const float* xrow0 = x + (size_t)(blockRow + r0) * F_DIM + kq;
    const float* xrow1 = x + (size_t)(blockRow + r0 + 64) * F_DIM + kq;
    float xn0 = 0.f, xn1 = 0.f;

    const int bslot0 = tid;     // 16B slot: row = s>>3, col16 = s&7

    // ---- prologue: chunk 0 into stage 0 ----
    {
        const char* shi = (const char*)g_whi;
        const char* slo = (const char*)g_wlo;
        #pragma unroll
        for (int o = 0; o < 2; ++o) {
            int s = bslot0 + o * 512;
            uint32_t d0 = sb + BHI_BY + (uint32_t)(s >> 3) * RS_BY + (uint32_t)(s & 7) * 16;
            CPA16(d0, shi + s * 16);
            uint32_t d1 = sb + BLO_BY + (uint32_t)(s >> 3) * RS_BY + (uint32_t)(s & 7) * 16;
            CPA16(d1, slo + s * 16);
        }
        CP_COMMIT();
        float4 a0 = *(const float4*)(xrow0);
        float4 a1 = *(const float4*)(xrow0 + 4);
        float4 a2 = *(const float4*)(xrow1);
        float4 a3 = *(const float4*)(xrow1 + 4);
        xn0 += conv8h(a0, a1, smc + AHI_BY + r0 * RS_BY + kq * 2);
        xn1 += conv8h(a2, a3, smc + AHI_BY + (r0 + 64) * RS_BY + kq * 2);
        CP_WAIT0();
    }
    __syncthreads();

    const uint32_t a_off = (uint32_t)((((lane >> 3) & 1) * 8 + (lane & 7)) * RS_BY
                                      + (lane >> 4) * 16);
    const uint32_t b_off = (uint32_t)(((lane >> 4) * 8 + (lane & 7)) * RS_BY
                                      + ((lane >> 3) & 1) * 16);
    const uint32_t a_row_by = (uint32_t)(wid_m * 32) * RS_BY;
    const uint32_t b_row_by = (uint32_t)(wid_n * 32) * RS_BY;

    float acc[2][4][4];
    #pragma unroll
    for (int i = 0; i < 2; ++i)
        #pragma unroll
        for (int j = 0; j < 4; ++j)
            #pragma unroll
            for (int k = 0; k < 4; ++k) acc[i][j][k] = 0.f;

    float4 pA0, pA1, pA2, pA3;

    #pragma unroll 1
    for (int c = 0; c < NCHUNK; ++c) {
        const int cur = c & 1;
        const uint32_t nbase = sb + (cur ^ 1) * STAGE_BY;

        // ---- issue async loads for chunk c+1 before the MMA section ----
        if (c < NCHUNK - 1) {
            const char* shi = (const char*)g_whi + (c + 1) * WCH_BY;
            const char* slo = (const char*)g_wlo + (c + 1) * WCH_BY;
            #pragma unroll
            for (int o = 0; o < 2; ++o) {
                int s = bslot0 + o * 512;
                uint32_t d0 = nbase + BHI_BY + (uint32_t)(s >> 3) * RS_BY + (uint32_t)(s & 7) * 16;
                CPA16(d0, shi + s * 16);
                uint32_t d1 = nbase + BLO_BY + (uint32_t)(s >> 3) * RS_BY + (uint32_t)(s & 7) * 16;
                CPA16(d1, slo + s * 16);
            }
            CP_COMMIT();
            const int kb = (c + 1) * KC;
            pA0 = *(const float4*)(xrow0 + kb);
            pA1 = *(const float4*)(xrow0 + kb + 4);
            pA2 = *(const float4*)(xrow1 + kb);
            pA3 = *(const float4*)(xrow1 + kb + 4);
        }

        // ---- MMA over current stage: 4 ks x (6 LDSM + 32 MMA) ----
        const uint32_t sbase = sb + cur * STAGE_BY;
        #pragma unroll
        for (int ks = 0; ks < 4; ++ks) {
            const uint32_t kby = ks * 32;
            uint32_t ahi[2][4], bhi[2][4], blo[2][4];
            #pragma unroll
            for (int mb = 0; mb < 2; ++mb) {
                uint32_t base = sbase + a_row_by + mb * 16 * RS_BY + kby + a_off;
                LDSM4(ahi[mb], base + AHI_BY);
            }
            #pragma unroll
            for (int nb = 0; nb < 2; ++nb) {
                uint32_t base = sbase + b_row_by + nb * 16 * RS_BY + kby + b_off;
                LDSM4(bhi[nb], base + BHI_BY);
                LDSM4(blo[nb], base + BLO_BY);
            }
            // term 1: all 16 tiles vs B-hi, then term 2 vs B-lo (dep dist = 16)
            #pragma unroll
            for (int mb = 0; mb < 2; ++mb)
                #pragma unroll
                for (int nf = 0; nf < 4; ++nf) {
                    const int nb = nf >> 1, h = (nf & 1) << 1;
                    MMA(acc[mb][nf], ahi[mb], bhi[nb][h], bhi[nb][h + 1]);
                }
            #pragma unroll
            for (int mb = 0; mb < 2; ++mb)
                #pragma unroll
                for (int nf = 0; nf < 4; ++nf) {
                    const int nb = nf >> 1, h = (nf & 1) << 1;
                    MMA(acc[mb][nf], ahi[mb], blo[nb][h], blo[nb][h + 1]);
                }
        }

        // ---- convert prefetched x into next stage ----
        if (c < NCHUNK - 1) {
            char* np = smc + (cur ^ 1) * STAGE_BY;
            xn0 += conv8h(pA0, pA1, np + AHI_BY + r0 * RS_BY + kq * 2);
            xn1 += conv8h(pA2, pA3, np + AHI_BY + (r0 + 64) * RS_BY + kq * 2);
        }
        CP_WAIT0();
        __syncthreads();
    }

    // ---------------- finalize xnorm (deterministic tree) -------------------
    smf[XPART_OFF + r0 * 8 + (tid & 7)] = xn0;
    smf[XPART_OFF + (r0 + 64) * 8 + (tid & 7)] = xn1;
    __syncthreads();
    if (tid < 128) {
        float s = 0.f;
        #pragma unroll
        for (int q = 0; q < 8; ++q) s += smf[XPART_OFF + tid * 8 + q];
        smf[XNORM_OFF + tid] = s;
    }
    __syncthreads();

    // ---------------- Epilogue: si from accum fragments -> SARR -------------
    #pragma unroll
    for (int mb = 0; mb < 2; ++mb) {
        const int rA = wid_m * 32 + mb * 16 + (lane >> 2);
        const float xnA = smf[XNORM_OFF + rA];
        const float xnB = smf[XNORM_OFF + rA + 8];
        #pragma unroll
        for (int nf = 0; nf < 4; ++nf) {
            const int cl = wid_n * 32 + nf * 8 + ((lane & 3) << 1);
            const float wn0 = smf[WNORM_OFF + cl], wn1 = smf[WNORM_OFF + cl + 1];
            const float g0 = smf[GAMMA_OFF + cl], g1 = smf[GAMMA_OFF + cl + 1];
            const float al0 = smf[ALPHA_OFF + cl], al1 = smf[ALPHA_OFF + cl + 1];
            float d00 = xnA + wn0 - 2.0f * acc[mb][nf][0];
            float d01 = xnA + wn1 - 2.0f * acc[mb][nf][1];
            float d10 = xnB + wn0 - 2.0f * acc[mb][nf][2];
            float d11 = xnB + wn1 - 2.0f * acc[mb][nf][3];
            smf[SARR_OFF + rA * SARR_STRIDE + cl]           = al0 * __expf(-g0 * d00);
            smf[SARR_OFF + rA * SARR_STRIDE + cl + 1]       = al1 * __expf(-g1 * d01);
            smf[SARR_OFF + (rA + 8) * SARR_STRIDE + cl]     = al0 * __expf(-g0 * d10);
            smf[SARR_OFF + (rA + 8) * SARR_STRIDE + cl + 1] = al1 * __expf(-g1 * d11);
        }
    }
    __syncthreads();

    // ---------------- DS combination scan (one thread per row) --------------
    if (tid < 128) {
        const int r = tid;
        float mx = 0.f;
        #pragma unroll 8
        for (int p = 0; p < P_DIM; ++p)
            mx = fmaxf(mx, smf[SARR_OFF + r * SARR_STRIDE + p]);
        const float invm = 1.0f / (mx + 1e-4f);

        float m1v[C_DIM + 1];
        {
            float s0 = smf[SARR_OFF + r * SARR_STRIDE + 0] * invm;
            #pragma unroll
            for (int c = 0; c < C_DIM; ++c) m1v[c] = smf[U_OFF + c * P_DIM + 0] * s0;
            m1v[C_DIM] = 1.0f - s0;
        }
        for (int p = 1; p < P_DIM; ++p) {
            float s  = smf[SARR_OFF + r * SARR_STRIDE + p] * invm;
            float o2 = 1.0f - s;
            float o1 = m1v[C_DIM];
            float cc[C_DIM + 1];
            #pragma unroll
            for (int c = 0; c < C_DIM; ++c) {
                float m2 = smf[U_OFF + c * P_DIM + p] * s;
                cc[c] = m1v[c] * m2 + m1v[c] * o2 + o1 * m2;
            }
            {
                float m2 = o2;
                cc[C_DIM] = m1v[C_DIM] * m2 + m1v[C_DIM] * o2 + o1 * m2;
            }
            if ((p & 3) == 0) {
                float csum = 0.f;
                #pragma unroll
                for (int c = 0; c <= C_DIM; ++c) csum += cc[c];
                float inv = __fdividef(1.0f, csum);
                #pragma unroll
                for (int c = 0; c <= C_DIM; ++c) m1v[c] = cc[c] * inv;
            } else {
                #pragma unroll
                for (int c = 0; c <= C_DIM; ++c) m1v[c] = cc[c];
            }
        }
        float tot = 0.f;
        #pragma unroll
        for (int c = 0; c <= C_DIM; ++c) tot += m1v[c];
        float inv = 1.0f / tot;
        float* op = out + (size_t)(blockRow + r) * (C_DIM + 1);
        #pragma unroll
        for (int c = 0; c <= C_DIM; ++c) op[c] = m1v[c] * inv;
    }
}

extern "C" void kernel_launch(void* const* d_in, const int* in_sizes, int n_in,
                              void* d_out, int out_size)
{
    const float* x    = (const float*)d_in[0];
    const float* w    = (const float*)d_in[1];
    const float* eta  = (const float*)d_in[2];
    const float* xi   = (const float*)d_in[3];
    const float* beta = (const float*)d_in[4];
    float* out = (float*)d_out;

    prep_kernel<<<128, 128>>>(w, eta, xi, beta);

    cudaFuncSetAttribute(ds_mma_kernel,
                         cudaFuncAttributeMaxDynamicSharedMemorySize, SMEM_ALLOC);
    ds_mma_kernel<<<B_TOTAL / MT, THREADS, SMEM_ALLOC>>>(x, out);
}